// round 7
// baseline (speedup 1.0000x reference)
#include <cuda_runtime.h>
#include <cuda_bf16.h>
#include <stdint.h>
#include <math.h>

// Problem constants: B=2, S=1024, E=2560, H=32, D=80, 3E=7680, BS=2048, K=2560

// ---------------- device scratch ----------------
__device__ float g_qkv[2048ull * 7680];
__device__ __nv_bfloat16 g_hid_hi[2048ull * 2560];
__device__ __nv_bfloat16 g_hid_lo[2048ull * 2560];
__device__ __nv_bfloat16 g_wqkvT_hi[7680ull * 2560];   // (N,K)
__device__ __nv_bfloat16 g_wqkvT_lo[7680ull * 2560];
__device__ __nv_bfloat16 g_wprojT_hi[2560ull * 2560];
__device__ __nv_bfloat16 g_wprojT_lo[2560ull * 2560];
__device__ __nv_bfloat16 g_attn_hi[2048ull * 2560];
__device__ __nv_bfloat16 g_attn_lo[2048ull * 2560];
__device__ __nv_bfloat16 g_Khi[64ull * 1024 * 88];     // [bh][key][88]
__device__ __nv_bfloat16 g_Klo[64ull * 1024 * 88];
__device__ __nv_bfloat16 g_Vthi[64ull * 80 * 1024];    // [bh][dim][1024]
__device__ __nv_bfloat16 g_Vtlo[64ull * 80 * 1024];

__device__ __forceinline__ uint32_t smem_u32(const void* p) {
    uint32_t a;
    asm("{ .reg .u64 t; cvta.to.shared.u64 t, %1; cvt.u32.u64 %0, t; }"
        : "=r"(a) : "l"(p));
    return a;
}

#define SWZ(o) ((uint32_t)(o) ^ ((((uint32_t)(o)) >> 3) & 0x70u))

#define CP16(s, g) \
    asm volatile("cp.async.cg.shared.global [%0], [%1], 16;" :: "r"(s), "l"(g))

#define LDSM4(r, addr) \
    asm volatile("ldmatrix.sync.aligned.m8n8.x4.shared.b16 {%0,%1,%2,%3}, [%4];" \
                 : "=r"((r)[0]), "=r"((r)[1]), "=r"((r)[2]), "=r"((r)[3]) \
                 : "r"(addr))

#define MMA_BF16(acc, A, b0, b1) \
    asm volatile("mma.sync.aligned.m16n8k16.row.col.f32.bf16.bf16.f32 " \
                 "{%0,%1,%2,%3}, {%4,%5,%6,%7}, {%8,%9}, {%0,%1,%2,%3};" \
                 : "+f"((acc)[0]), "+f"((acc)[1]), "+f"((acc)[2]), "+f"((acc)[3]) \
                 : "r"((A)[0]), "r"((A)[1]), "r"((A)[2]), "r"((A)[3]), \
                   "r"(b0), "r"(b1))

// ---------------------------------------------------------------------------
// Conversion: fp32 -> bf16 hi/lo
// ---------------------------------------------------------------------------
__global__ void conv_hilo(const float* __restrict__ X,
                          __nv_bfloat16* __restrict__ Hh,
                          __nv_bfloat16* __restrict__ Ll, int n4) {
    int i = blockIdx.x * blockDim.x + threadIdx.x;
    if (i >= n4) return;
    float4 v = ((const float4*)X)[i];
    __nv_bfloat16 h0 = __float2bfloat16(v.x), h1 = __float2bfloat16(v.y);
    __nv_bfloat16 h2 = __float2bfloat16(v.z), h3 = __float2bfloat16(v.w);
    __nv_bfloat162 a, b;
    a.x = h0; a.y = h1; b.x = h2; b.y = h3;
    ((__nv_bfloat162*)Hh)[i * 2] = a;
    ((__nv_bfloat162*)Hh)[i * 2 + 1] = b;
    __nv_bfloat162 c, d;
    c.x = __float2bfloat16(v.x - __bfloat162float(h0));
    c.y = __float2bfloat16(v.y - __bfloat162float(h1));
    d.x = __float2bfloat16(v.z - __bfloat162float(h2));
    d.y = __float2bfloat16(v.w - __bfloat162float(h3));
    ((__nv_bfloat162*)Ll)[i * 2] = c;
    ((__nv_bfloat162*)Ll)[i * 2 + 1] = d;
}

// ---------------------------------------------------------------------------
// Transpose + convert: W (K,N) fp32 -> Th/Tl (N,K) bf16
// ---------------------------------------------------------------------------
__global__ void transpose_conv(const float* __restrict__ W,
                               __nv_bfloat16* __restrict__ Th,
                               __nv_bfloat16* __restrict__ Tl, int K, int N) {
    __shared__ float t[32][33];
    int n0 = blockIdx.x * 32, k0 = blockIdx.y * 32;
    int tx = threadIdx.x, ty = threadIdx.y;
#pragma unroll
    for (int j = 0; j < 4; j++)
        t[ty + j * 8][tx] = W[(size_t)(k0 + ty + j * 8) * N + n0 + tx];
    __syncthreads();
#pragma unroll
    for (int j = 0; j < 4; j++) {
        float v = t[tx][ty + j * 8];
        __nv_bfloat16 h = __float2bfloat16(v);
        size_t o = (size_t)(n0 + ty + j * 8) * K + k0 + tx;
        Th[o] = h;
        Tl[o] = __float2bfloat16(v - __bfloat162float(h));
    }
}

// ---------------------------------------------------------------------------
// prep_k: k part of qkv -> bf16 hi/lo [bh][key][88]
// ---------------------------------------------------------------------------
__global__ void prep_k(const float* __restrict__ qkv,
                       __nv_bfloat16* __restrict__ Kh,
                       __nv_bfloat16* __restrict__ Kl) {
    int idx = blockIdx.x * 256 + threadIdx.x;
    if (idx >= 64 * 1024 * 80) return;
    int d = idx % 80;
    int key = (idx / 80) & 1023;
    int bh = idx / 81920;
    int b = bh >> 5, h = bh & 31;
    float v = qkv[(size_t)(b * 1024 + key) * 7680 + 2560 + h * 80 + d];
    __nv_bfloat16 hh = __float2bfloat16(v);
    size_t o = (size_t)bh * 90112 + key * 88 + d;
    Kh[o] = hh;
    Kl[o] = __float2bfloat16(v - __bfloat162float(hh));
}

// ---------------------------------------------------------------------------
// prep_vt: v part -> transposed bf16 hi/lo [bh][dim][1024]
// ---------------------------------------------------------------------------
__global__ void prep_vt(const float* __restrict__ qkv,
                        __nv_bfloat16* __restrict__ Vh,
                        __nv_bfloat16* __restrict__ Vl) {
    __shared__ float t[64][17];
    int kt = blockIdx.x, dt = blockIdx.y, bh = blockIdx.z;
    int b = bh >> 5, h = bh & 31;
    int tx = threadIdx.x, ty = threadIdx.y;
#pragma unroll
    for (int j = 0; j < 4; j++) {
        int key = kt * 64 + ty + j * 16;
        t[ty + j * 16][tx] = qkv[(size_t)(b * 1024 + key) * 7680 + 5120 +
                                 h * 80 + dt * 16 + tx];
    }
    __syncthreads();
    size_t ob = ((size_t)bh * 80 + dt * 16 + ty) * 1024 + kt * 64;
#pragma unroll
    for (int j = 0; j < 4; j++) {
        float v = t[tx + j * 16][ty];
        __nv_bfloat16 hh = __float2bfloat16(v);
        Vh[ob + tx + j * 16] = hh;
        Vl[ob + tx + j * 16] = __float2bfloat16(v - __bfloat162float(hh));
    }
}

// ---------------------------------------------------------------------------
// mma.sync bf16x3 GEMM: C(2048,N) = A @ B^T + bias
// CTA 128x128, 256 threads, warp tile 64x32 (mw 0..1, nw 0..3).
// K chunks of 64, 3-stage cp.async pipeline (192KB smem).
// ---------------------------------------------------------------------------
__global__ __launch_bounds__(256, 1) void gemm_bf16x3(
    const __nv_bfloat16* __restrict__ Ah, const __nv_bfloat16* __restrict__ Al,
    const __nv_bfloat16* __restrict__ Bh, const __nv_bfloat16* __restrict__ Bl,
    const float* __restrict__ bias, float* __restrict__ C, int N) {
    extern __shared__ __align__(1024) char dsm[];
    const uint32_t base = smem_u32(dsm);

    const int tid = threadIdx.x;
    const int wid = tid >> 5, lane = tid & 31;
    const int mw = wid & 1;       // 2 x 64 rows
    const int nw = wid >> 1;      // 4 x 32 cols
    const int mt = blockIdx.y, nt = blockIdx.x;
    const int K = 2560;

    const int trow = tid >> 3;    // 0..31
    const int tkg = tid & 7;

    float acc[4][4][4];
#pragma unroll
    for (int a = 0; a < 4; a++)
#pragma unroll
        for (int b = 0; b < 4; b++)
#pragma unroll
            for (int c = 0; c < 4; c++) acc[a][b][c] = 0.0f;

    auto load_chunk = [&](int c, int st) {
        const int k0 = c * 64;
        const uint32_t s0 = base + st * 65536;
#pragma unroll
        for (int j = 0; j < 4; j++) {
            const int row = j * 32 + trow;
            const uint32_t so = SWZ(row * 128 + tkg * 16);
            const __nv_bfloat16* ga = Ah + (size_t)(mt * 128 + row) * K + k0 + tkg * 8;
            const __nv_bfloat16* gal = Al + (size_t)(mt * 128 + row) * K + k0 + tkg * 8;
            const __nv_bfloat16* gb = Bh + (size_t)(nt * 128 + row) * K + k0 + tkg * 8;
            const __nv_bfloat16* gbl = Bl + (size_t)(nt * 128 + row) * K + k0 + tkg * 8;
            CP16(s0 + so, ga);
            CP16(s0 + 16384 + so, gal);
            CP16(s0 + 32768 + so, gb);
            CP16(s0 + 49152 + so, gbl);
        }
        asm volatile("cp.async.commit_group;");
    };

    const int lr = lane & 15;
    const int lc = (lane >> 4) * 16;

    load_chunk(0, 0);
    load_chunk(1, 1);

    int st = 0;
    for (int c = 0; c < 40; c++) {
        if (c < 39) {
            asm volatile("cp.async.wait_group 1;");
        } else {
            asm volatile("cp.async.wait_group 0;");
        }
        __syncthreads();
        if (c + 2 < 40) {
            int st2 = st + 2;
            if (st2 >= 3) st2 -= 3;
            load_chunk(c + 2, st2);
        }

        const uint32_t sA = base + st * 65536;
#pragma unroll
        for (int ks = 0; ks < 4; ks++) {
            uint32_t ah[4][4], al[4][4];
#pragma unroll
            for (int mb = 0; mb < 4; mb++) {
                const uint32_t ro = (mw * 64 + mb * 16 + lr) * 128 + ks * 32 + lc;
                LDSM4(ah[mb], sA + SWZ(ro));
                LDSM4(al[mb], sA + 16384 + SWZ(ro));
            }
            uint32_t bh2[2][4], bl2[2][4];
#pragma unroll
            for (int nb = 0; nb < 2; nb++) {
                const uint32_t ro = (nw * 32 + nb * 16 + lr) * 128 + ks * 32 + lc;
                LDSM4(bh2[nb], sA + 32768 + SWZ(ro));
                LDSM4(bl2[nb], sA + 49152 + SWZ(ro));
            }
            // term-major: acc reuse distance = 16 MMAs
#pragma unroll
            for (int mb = 0; mb < 4; mb++)
#pragma unroll
                for (int nb = 0; nb < 2; nb++) {
                    MMA_BF16(acc[mb][nb * 2],     ah[mb], bh2[nb][0], bh2[nb][2]);
                    MMA_BF16(acc[mb][nb * 2 + 1], ah[mb], bh2[nb][1], bh2[nb][3]);
                }
#pragma unroll
            for (int mb = 0; mb < 4; mb++)
#pragma unroll
                for (int nb = 0; nb < 2; nb++) {
                    MMA_BF16(acc[mb][nb * 2],     ah[mb], bl2[nb][0], bl2[nb][2]);
                    MMA_BF16(acc[mb][nb * 2 + 1], ah[mb], bl2[nb][1], bl2[nb][3]);
                }
#pragma unroll
            for (int mb = 0; mb < 4; mb++)
#pragma unroll
                for (int nb = 0; nb < 2; nb++) {
                    MMA_BF16(acc[mb][nb * 2],     al[mb], bh2[nb][0], bh2[nb][2]);
                    MMA_BF16(acc[mb][nb * 2 + 1], al[mb], bh2[nb][1], bh2[nb][3]);
                }
        }
        st++;
        if (st >= 3) st -= 3;
    }

    const int row0 = mt * 128 + mw * 64 + (lane >> 2);
    const int col0 = nt * 128 + nw * 32 + 2 * (lane & 3);
#pragma unroll
    for (int mb = 0; mb < 4; mb++) {
#pragma unroll
        for (int n8 = 0; n8 < 4; n8++) {
            const int gc = col0 + n8 * 8;
            const float b0 = bias[gc], b1 = bias[gc + 1];
            const int r = row0 + mb * 16;
            float2 o0 = make_float2(acc[mb][n8][0] + b0, acc[mb][n8][1] + b1);
            float2 o1 = make_float2(acc[mb][n8][2] + b0, acc[mb][n8][3] + b1);
            *(float2*)&C[(size_t)r * N + gc] = o0;
            *(float2*)&C[(size_t)(r + 8) * N + gc] = o1;
        }
    }
}

// ---------------------------------------------------------------------------
// attn_mma v3: Q fragments hoisted into registers across all K-tiles.
// smem layout identical to v2.
// ---------------------------------------------------------------------------
#define A_OFF_QH 0u
#define A_OFF_QL 11264u
#define A_OFF_K  22528u
#define A_K_STG  45056u
#define A_OFF_SC 112640u
#define A_OFF_PH 0u
#define A_OFF_PL 33024u
#define A_OFF_V 67584u
#define A_OFF_RED 154624u
#define A_SMEM 197632

__global__ __launch_bounds__(256, 1) void attn_mma(
    const float* __restrict__ qkv,
    const __nv_bfloat16* __restrict__ Kh, const __nv_bfloat16* __restrict__ Kl,
    const __nv_bfloat16* __restrict__ Vh, const __nv_bfloat16* __restrict__ Vl,
    const float* __restrict__ gm, const float* __restrict__ gp,
    const float* __restrict__ ga, const float* __restrict__ qp,
    const float* __restrict__ isr,
    __nv_bfloat16* __restrict__ out_hi, __nv_bfloat16* __restrict__ out_lo) {
    extern __shared__ __align__(128) char smc[];
    __shared__ float coeff[240];
    __shared__ float row_l[16];
    char* sm = smc;
    const uint32_t base = smem_u32(smc);

    const int tid = threadIdx.x;
    const int wid = tid >> 5, lane = tid & 31;
    const int lr = lane & 15, lc = (lane >> 4) << 4;
    const int rr = lane >> 2, cc = (lane & 3) * 2;
    const int bh = blockIdx.y, b = bh >> 5, h = bh & 31;
    const int q0 = blockIdx.x * 16;

    const __nv_bfloat16* KhB = Kh + (size_t)bh * 90112;
    const __nv_bfloat16* KlB = Kl + (size_t)bh * 90112;
    auto load_k = [&](int kt, int stg) {
        const uint32_t sb = base + A_OFF_K + (uint32_t)stg * A_K_STG;
#pragma unroll
        for (int j = 0; j < 11; j++) {
            int idx = tid + j * 256;
            int m = idx >= 1408;
            int rem = m ? idx - 1408 : idx;
            int row = rem / 11, ch = rem - row * 11;
            const __nv_bfloat16* g =
                (m ? KlB : KhB) + (size_t)(kt * 128 + row) * 88 + ch * 8;
            CP16(sb + m * 22528u + row * 176 + ch * 16, g);
        }
        asm volatile("cp.async.commit_group;");
    };

    load_k(0, 0);

    if (tid < 240) {
        int g = tid / 80, d = tid - g * 80;
        float r0 = gm[g * 4 + 0] + gm[g * 4 + 1];
        float r1 = gm[g * 4 + 2] + gm[g * 4 + 3];
        float ph = gp[g * 80 + d];
        coeff[tid] = (cosf(ph) * r0 + sinf(ph) * r1) * ga[g * 80 + d];
    }
    __syncthreads();

    // build Qext (4 variants x 16 rows x 80 dims, scale folded in)
    const float scale = rsqrtf(80.0f);
    for (int idx = tid; idx < 1280; idx += 256) {
        int r = idx / 80, d = idx - r * 80;
        float v = qkv[(size_t)(b * 1024 + q0 + r) * 7680 + h * 80 + d] * scale;
        float vv[4] = {v, v * coeff[d], v * coeff[80 + d], v * coeff[160 + d]};
#pragma unroll
        for (int g = 0; g < 4; g++) {
            uint32_t o = (g * 16 + r) * 176 + d * 2;
            __nv_bfloat16 hh = __float2bfloat16(vv[g]);
            *(__nv_bfloat16*)(sm + A_OFF_QH + o) = hh;
            *(__nv_bfloat16*)(sm + A_OFF_QL + o) =
                __float2bfloat16(vv[g] - __bfloat162float(hh));
        }
    }
    __syncthreads();

    // hoist Q fragments into registers (kt-invariant)
    uint32_t qH[5][4][4], qL[5][4][4];
#pragma unroll
    for (int ks = 0; ks < 5; ks++) {
#pragma unroll
        for (int g = 0; g < 4; g++) {
            uint32_t ro = (g * 16 + lr) * 176 + ks * 32 + lc;
            LDSM4(qH[ks][g], base + A_OFF_QH + ro);
            LDSM4(qL[ks][g], base + A_OFF_QL + ro);
        }
    }

    const float intf = isr[0] * (1.0f / 3.0f);
    float* sc = (float*)(sm + A_OFF_SC);     // 16 x 1032

    // ---- Phase 1: scores; warp wid owns keys [kt*128 + wid*16, +16) ----
    for (int kt = 0; kt < 8; kt++) {
        const int stg = kt & 1;
        asm volatile("cp.async.wait_group 0;");
        __syncthreads();
        if (kt < 7) load_k(kt + 1, stg ^ 1);

        const uint32_t kbase = base + A_OFF_K + (uint32_t)stg * A_K_STG;
        float acc[4][2][4];
#pragma unroll
        for (int g = 0; g < 4; g++)
#pragma unroll
            for (int i = 0; i < 2; i++)
#pragma unroll
                for (int j = 0; j < 4; j++) acc[g][i][j] = 0.0f;

#pragma unroll
        for (int ks = 0; ks < 5; ks++) {
            uint32_t bH[4], bL[4];
            uint32_t rb = (wid * 16 + lr) * 176 + ks * 32 + lc;
            LDSM4(bH, kbase + rb);
            LDSM4(bL, kbase + 22528u + rb);
#pragma unroll
            for (int g = 0; g < 4; g++) {
                MMA_BF16(acc[g][0], qH[ks][g], bH[0], bH[2]);
                MMA_BF16(acc[g][1], qH[ks][g], bH[1], bH[3]);
            }
#pragma unroll
            for (int g = 0; g < 4; g++) {
                MMA_BF16(acc[g][0], qH[ks][g], bL[0], bL[2]);
                MMA_BF16(acc[g][1], qH[ks][g], bL[1], bL[3]);
            }
#pragma unroll
            for (int g = 0; g < 4; g++) {
                MMA_BF16(acc[g][0], qL[ks][g], bH[0], bH[2]);
                MMA_BF16(acc[g][1], qL[ks][g], bH[1], bH[3]);
            }
        }

        // combine interference in registers, write final fp32 scores
#pragma unroll
        for (int n8 = 0; n8 < 2; n8++) {
#pragma unroll
            for (int j = 0; j < 4; j++) {
                int r = rr + (j >> 1) * 8;
                int c = kt * 128 + wid * 16 + n8 * 8 + cc + (j & 1);
                float s  = acc[0][n8][j];
                float a0 = acc[1][n8][j];
                float a1 = acc[2][n8][j];
                float a2 = acc[3][n8][j];
                sc[r * 1032 + c] = s + (a0 * a1 + a0 * a2 + a1 * a2) * intf;
            }
        }
    }
    __syncthreads();

    // ---- Phase 2: softmax -> P (bf16 hi/lo) ----
#pragma unroll
    for (int t2 = 0; t2 < 2; t2++) {
        int r = wid * 2 + t2;
        const float* row = sc + r * 1032;
        float mx = -1e30f;
#pragma unroll 8
        for (int j = 0; j < 32; j++) mx = fmaxf(mx, row[lane + j * 32]);
#pragma unroll
        for (int off = 16; off > 0; off >>= 1)
            mx = fmaxf(mx, __shfl_xor_sync(0xffffffffu, mx, off));
        float sum = 0.0f;
#pragma unroll 8
        for (int j = 0; j < 32; j++) {
            int c = lane + j * 32;
            float p = __expf(row[c] - mx);
            sum += p;
            __nv_bfloat16 hh = __float2bfloat16(p);
            *(__nv_bfloat16*)(sm + A_OFF_PH + r * 2064 + c * 2) = hh;
            *(__nv_bfloat16*)(sm + A_OFF_PL + r * 2064 + c * 2) =
                __float2bfloat16(p - __bfloat162float(hh));
        }
#pragma unroll
        for (int off = 16; off > 0; off >>= 1)
            sum += __shfl_xor_sync(0xffffffffu, sum, off);
        if (lane == 0) row_l[r] = sum;
    }
    __syncthreads();

    // ---- Phase 3: P @ V ----
    const __nv_bfloat16* VhB = Vh + (size_t)bh * 81920;
    const __nv_bfloat16* VlB = Vl + (size_t)bh * 81920;
    auto load_v = [&](int kt, int stg) {
#pragma unroll
        for (int j = 0; j < 10; j++) {
            int idx = tid + j * 256;
            int m = idx >= 1280;
            int rem = m ? idx - 1280 : idx;
            int dim = rem >> 4, ch = rem & 15;
            const __nv_bfloat16* g =
                (m ? VlB : VhB) + (size_t)dim * 1024 + kt * 128 + ch * 8;
            CP16(base + A_OFF_V + stg * 43520 + m * 21760 + dim * 272 + ch * 16, g);
        }
        asm volatile("cp.async.commit_group;");
    };

    load_v(0, 0);
    float acc[10][4];
#pragma unroll
    for (int i = 0; i < 10; i++)
#pragma unroll
        for (int j = 0; j < 4; j++) acc[i][j] = 0.0f;

    for (int kt = 0; kt < 8; kt++) {
        const int stg = kt & 1;
        if (kt < 7) {
            load_v(kt + 1, stg ^ 1);
            asm volatile("cp.async.wait_group 1;");
        } else {
            asm volatile("cp.async.wait_group 0;");
        }
        __syncthreads();

        uint32_t aH[4], aL[4];
        uint32_t ro = lr * 2064 + kt * 256 + wid * 32 + lc;
        LDSM4(aH, base + A_OFF_PH + ro);
        LDSM4(aL, base + A_OFF_PL + ro);
        uint32_t bH[5][4], bL[5][4];
#pragma unroll
        for (int nd = 0; nd < 5; nd++) {
            uint32_t rb = stg * 43520 + (nd * 16 + lr) * 272 + wid * 32 + lc;
            LDSM4(bH[nd], base + A_OFF_V + rb);
            LDSM4(bL[nd], base + A_OFF_V + 21760 + rb);
        }
#pragma unroll
        for (int nd = 0; nd < 5; nd++) {
            MMA_BF16(acc[nd * 2],     aH, bH[nd][0], bH[nd][2]);
            MMA_BF16(acc[nd * 2 + 1], aH, bH[nd][1], bH[nd][3]);
        }
#pragma unroll
        for (int nd = 0; nd < 5; nd++) {
            MMA_BF16(acc[nd * 2],     aH, bL[nd][0], bL[nd][2]);
            MMA_BF16(acc[nd * 2 + 1], aH, bL[nd][1], bL[nd][3]);
        }
#pragma unroll
        for (int nd = 0; nd < 5; nd++) {
            MMA_BF16(acc[nd * 2],     aL, bH[nd][0], bH[nd][2]);
            MMA_BF16(acc[nd * 2 + 1], aL, bH[nd][1], bH[nd][3]);
        }
        __syncthreads();
    }

    float* red = (float*)(sm + A_OFF_RED);
    float* redw = red + wid * 1344;
#pragma unroll
    for (int j = 0; j < 10; j++) {
        int d = (j >> 1) * 16 + (j & 1) * 8 + cc;
        redw[rr * 84 + d]           = acc[j][0];
        redw[rr * 84 + d + 1]       = acc[j][1];
        redw[(rr + 8) * 84 + d]     = acc[j][2];
        redw[(rr + 8) * 84 + d + 1] = acc[j][3];
    }
    __syncthreads();

    const float cph = cosf(qp[h]);
    for (int idx = tid; idx < 1280; idx += 256) {
        int r = idx / 80, d = idx - r * 80;
        float s = 0.0f;
#pragma unroll
        for (int w = 0; w < 8; w++) s += red[w * 1344 + r * 84 + d];
        float o = s * cph / row_l[r];
        size_t go = (size_t)(b * 1024 + q0 + r) * 2560 + h * 80 + d;
        __nv_bfloat16 hh = __float2bfloat16(o);
        out_hi[go] = hh;
        out_lo[go] = __float2bfloat16(o - __bfloat162float(hh));
    }
}

// ---------------------------------------------------------------------------
extern "C" void kernel_launch(void* const* d_in, const int* in_sizes, int n_in,
                              void* d_out, int out_size) {
    const float* hidden = (const float*)d_in[0];
    const float* Wqkv   = (const float*)d_in[1];
    const float* bqkv   = (const float*)d_in[2];
    const float* Wproj  = (const float*)d_in[3];
    const float* bproj  = (const float*)d_in[4];
    const float* gm     = (const float*)d_in[5];
    const float* gp     = (const float*)d_in[6];
    const float* ga     = (const float*)d_in[7];
    const float* qp     = (const float*)d_in[8];
    const float* isr    = (const float*)d_in[9];
    float* out = (float*)d_out;

    void *p_qkv, *p_hh, *p_hl, *p_wqh, *p_wql, *p_wph, *p_wpl, *p_ah, *p_al;
    void *p_kh, *p_kl, *p_vh, *p_vl;
    cudaGetSymbolAddress(&p_qkv, g_qkv);
    cudaGetSymbolAddress(&p_hh, g_hid_hi);
    cudaGetSymbolAddress(&p_hl, g_hid_lo);
    cudaGetSymbolAddress(&p_wqh, g_wqkvT_hi);
    cudaGetSymbolAddress(&p_wql, g_wqkvT_lo);
    cudaGetSymbolAddress(&p_wph, g_wprojT_hi);
    cudaGetSymbolAddress(&p_wpl, g_wprojT_lo);
    cudaGetSymbolAddress(&p_ah, g_attn_hi);
    cudaGetSymbolAddress(&p_al, g_attn_lo);
    cudaGetSymbolAddress(&p_kh, g_Khi);
    cudaGetSymbolAddress(&p_kl, g_Klo);
    cudaGetSymbolAddress(&p_vh, g_Vthi);
    cudaGetSymbolAddress(&p_vl, g_Vtlo);

    const int GEMM_SMEM = 3 * 65536;
    cudaFuncSetAttribute(gemm_bf16x3,
                         cudaFuncAttributeMaxDynamicSharedMemorySize, GEMM_SMEM);
    cudaFuncSetAttribute(attn_mma,
                         cudaFuncAttributeMaxDynamicSharedMemorySize, A_SMEM);

    // 1) input conversions
    conv_hilo<<<5120, 256>>>(hidden, (__nv_bfloat16*)p_hh, (__nv_bfloat16*)p_hl,
                             2048 * 2560 / 4);
    transpose_conv<<<dim3(7680 / 32, 2560 / 32), dim3(32, 8)>>>(
        Wqkv, (__nv_bfloat16*)p_wqh, (__nv_bfloat16*)p_wql, 2560, 7680);
    transpose_conv<<<dim3(2560 / 32, 2560 / 32), dim3(32, 8)>>>(
        Wproj, (__nv_bfloat16*)p_wph, (__nv_bfloat16*)p_wpl, 2560, 2560);

    // 2) qkv = hidden @ Wqkv + bqkv
    gemm_bf16x3<<<dim3(60, 16), 256, GEMM_SMEM>>>(
        (const __nv_bfloat16*)p_hh, (const __nv_bfloat16*)p_hl,
        (const __nv_bfloat16*)p_wqh, (const __nv_bfloat16*)p_wql,
        bqkv, (float*)p_qkv, 7680);

    // 3) K/V conversion for tensor-core attention
    prep_k<<<20480, 256>>>((const float*)p_qkv, (__nv_bfloat16*)p_kh,
                           (__nv_bfloat16*)p_kl);
    prep_vt<<<dim3(16, 5, 64), dim3(16, 16)>>>(
        (const float*)p_qkv, (__nv_bfloat16*)p_vh, (__nv_bfloat16*)p_vl);

    // 4) tensor-core quantum attention -> bf16 hi/lo
    attn_mma<<<dim3(64, 64), 256, A_SMEM>>>(
        (const float*)p_qkv,
        (const __nv_bfloat16*)p_kh, (const __nv_bfloat16*)p_kl,
        (const __nv_bfloat16*)p_vh, (const __nv_bfloat16*)p_vl,
        gm, gp, ga, qp, isr,
        (__nv_bfloat16*)p_ah, (__nv_bfloat16*)p_al);

    // 5) out = attn @ Wproj + bproj
    gemm_bf16x3<<<dim3(20, 16), 256, GEMM_SMEM>>>(
        (const __nv_bfloat16*)p_ah, (const __nv_bfloat16*)p_al,
        (const __nv_bfloat16*)p_wph, (const __nv_bfloat16*)p_wpl,
        bproj, out, 2560);
}